// round 1
// baseline (speedup 1.0000x reference)
#include <cuda_runtime.h>
#include <math.h>

#define BATCH   2
#define SEQ     2048
#define DMODEL  4096
#define NHEADS  32
#define NKV     8
#define HD      128
#define QKVD    6144            // (32 + 2*8) * 128
#define MTOK    (BATCH * SEQ)   // 4096

// Scratch buffers (allocation-free rule: __device__ globals)
__device__ float g_qkv[(size_t)MTOK * QKVD];    // 96 MB
__device__ float g_attn[(size_t)MTOK * DMODEL]; // 64 MB

// ---------------------------------------------------------------------------
// Classic 128x128x8 register-blocked SGEMM, 256 threads, 8x8 per thread.
// M, N, K all multiples of 128 here -> no bounds checks.
// C[M,N] = A[M,K] @ B[K,N], all row-major fp32.
// ---------------------------------------------------------------------------
__global__ __launch_bounds__(256) void sgemm128(
    const float* __restrict__ A, const float* __restrict__ Bm,
    float* __restrict__ C, int M, int N, int K)
{
    __shared__ float As[8][128];   // transposed A tile
    __shared__ float Bs[8][128];

    const int tid = threadIdx.x;
    const float* Ab = A + (size_t)blockIdx.y * 128 * K;
    const float* Bb = Bm + (size_t)blockIdx.x * 128;
    float* Cb = C + (size_t)blockIdx.y * 128 * N + (size_t)blockIdx.x * 128;

    const int aRow = tid >> 1, aCol = (tid & 1) << 2;   // A tile: 128 x 8
    const int bRow = tid >> 5, bCol = (tid & 31) << 2;  // B tile: 8 x 128
    const int tRow = (tid >> 4) << 3;                   // 0..120 step 8
    const int tCol = (tid & 15) << 3;

    float acc[8][8] = {};

    for (int kb = 0; kb < K; kb += 8) {
        float4 av = *(const float4*)(Ab + (size_t)aRow * K + kb + aCol);
        As[aCol + 0][aRow] = av.x;
        As[aCol + 1][aRow] = av.y;
        As[aCol + 2][aRow] = av.z;
        As[aCol + 3][aRow] = av.w;
        *(float4*)(&Bs[bRow][bCol]) =
            *(const float4*)(Bb + (size_t)(kb + bRow) * N + bCol);
        __syncthreads();

        #pragma unroll
        for (int k = 0; k < 8; k++) {
            float rm[8], rn[8];
            *(float4*)&rm[0] = *(float4*)&As[k][tRow];
            *(float4*)&rm[4] = *(float4*)&As[k][tRow + 4];
            *(float4*)&rn[0] = *(float4*)&Bs[k][tCol];
            *(float4*)&rn[4] = *(float4*)&Bs[k][tCol + 4];
            #pragma unroll
            for (int i = 0; i < 8; i++)
                #pragma unroll
                for (int j = 0; j < 8; j++)
                    acc[i][j] += rm[i] * rn[j];
        }
        __syncthreads();
    }

    #pragma unroll
    for (int i = 0; i < 8; i++) {
        float* cr = Cb + (size_t)(tRow + i) * N + tCol;
        *(float4*)cr       = make_float4(acc[i][0], acc[i][1], acc[i][2], acc[i][3]);
        *((float4*)cr + 1) = make_float4(acc[i][4], acc[i][5], acc[i][6], acc[i][7]);
    }
}

// ---------------------------------------------------------------------------
// RoPE in-place on Q (heads 0..31) and K (heads 32..39) parts of qkv.
// grid: (MTOK, 40), block: 64. cos/sin are [SEQ, 128] with cos[d]==cos[d+64].
// ---------------------------------------------------------------------------
__global__ void rope_kernel(float* __restrict__ qkv,
                            const float* __restrict__ cosT,
                            const float* __restrict__ sinT)
{
    const int token = blockIdx.x;   // b*SEQ + s
    const int head  = blockIdx.y;   // 0..39 (q heads then k heads, contiguous)
    const int s = token & (SEQ - 1);
    const int d = threadIdx.x;      // 0..63

    float* p = qkv + (size_t)token * QKVD + head * HD;
    const float c  = cosT[s * HD + d];
    const float sn = sinT[s * HD + d];
    const float x1 = p[d];
    const float x2 = p[d + 64];
    p[d]      = x1 * c - x2 * sn;
    p[d + 64] = x2 * c + x1 * sn;
}

// ---------------------------------------------------------------------------
// FP32 flash attention, causal GQA. BQ = BK = 64, 256 threads.
// Q/K stored transposed in smem (conflict-free float4 reads in the dot loop),
// P stored transposed (conflict-free float4 reads in the PV loop and
// conflict-free per-row softmax across 2 warps).
// smem (floats): Qt 128*68 | Kt 128*68 | Vs 64*128 | Pt 64*68 | m,l,alpha 3*64
// ---------------------------------------------------------------------------
#define QT_LD 68
#define FLASH_SMEM_FLOATS (128*QT_LD*2 + 64*128 + 64*QT_LD + 3*64)
#define FLASH_SMEM_BYTES  (FLASH_SMEM_FLOATS * 4)

__global__ __launch_bounds__(256) void flash_kernel(
    const float* __restrict__ qkv, float* __restrict__ attn)
{
    extern __shared__ float sm[];
    float* Qt = sm;                     // [128][68]  Qt[d][r]
    float* Kt = Qt + 128 * QT_LD;       // [128][68]  Kt[d][c]
    float* Vs = Kt + 128 * QT_LD;       // [64][128]  Vs[c][d]
    float* Pt = Vs + 64 * 128;          // [64][68]   Pt[c][r]
    float* mS = Pt + 64 * QT_LD;
    float* lS = mS + 64;
    float* aS = lS + 64;

    const int tid = threadIdx.x;
    const int qt  = blockIdx.x;         // q tile 0..31
    const int bh  = blockIdx.y;         // 0..63
    const int b   = bh >> 5;
    const int h   = bh & 31;
    const int kvh = h >> 2;
    const int q0  = qt * 64;
    const float scale = 0.08838834764831845f;   // 128^-0.5

    const float* Qg = qkv + (size_t)b * SEQ * QKVD + (size_t)h * HD;
    const float* Kg = qkv + (size_t)b * SEQ * QKVD + NHEADS * HD + (size_t)kvh * HD;
    const float* Vg = Kg + NKV * HD;

    // Load Q tile transposed (64 rows x 128 dims)
    #pragma unroll
    for (int i = 0; i < 8; i++) {
        int idx = i * 256 + tid;                 // 0..2047
        int r = idx >> 5, d4 = (idx & 31) << 2;
        float4 v = *(const float4*)(Qg + (size_t)(q0 + r) * QKVD + d4);
        Qt[(d4 + 0) * QT_LD + r] = v.x;
        Qt[(d4 + 1) * QT_LD + r] = v.y;
        Qt[(d4 + 2) * QT_LD + r] = v.z;
        Qt[(d4 + 3) * QT_LD + r] = v.w;
    }
    if (tid < 64) { mS[tid] = -INFINITY; lS[tid] = 0.f; }

    const int rt = tid >> 4, ct = tid & 15;
    const int rbase = rt << 2;          // 4 q-rows per thread
    const int cS = ct << 2;             // 4 key-cols per thread (S phase)
    const int cV = ct << 3;             // 8 v-cols per thread (PV phase)

    float O[4][8];
    #pragma unroll
    for (int j = 0; j < 4; j++)
        #pragma unroll
        for (int i = 0; i < 8; i++) O[j][i] = 0.f;

    for (int kt = 0; kt <= qt; kt++) {
        const int k0 = kt * 64;
        __syncthreads();   // previous iteration done with Kt/Vs/Pt

        // Load K transposed + V natural
        #pragma unroll
        for (int i = 0; i < 8; i++) {
            int idx = i * 256 + tid;
            int r = idx >> 5, d4 = (idx & 31) << 2;
            float4 kv = *(const float4*)(Kg + (size_t)(k0 + r) * QKVD + d4);
            Kt[(d4 + 0) * QT_LD + r] = kv.x;
            Kt[(d4 + 1) * QT_LD + r] = kv.y;
            Kt[(d4 + 2) * QT_LD + r] = kv.z;
            Kt[(d4 + 3) * QT_LD + r] = kv.w;
            float4 vv = *(const float4*)(Vg + (size_t)(k0 + r) * QKVD + d4);
            *(float4*)(Vs + r * 128 + d4) = vv;
        }
        __syncthreads();

        // S = Q K^T (64x64), each thread 4x4
        float acc[4][4] = {};
        #pragma unroll 8
        for (int d = 0; d < 128; d++) {
            float4 qv = *(float4*)(Qt + d * QT_LD + rbase);
            float4 kv = *(float4*)(Kt + d * QT_LD + cS);
            float q[4] = {qv.x, qv.y, qv.z, qv.w};
            float k[4] = {kv.x, kv.y, kv.z, kv.w};
            #pragma unroll
            for (int j = 0; j < 4; j++)
                #pragma unroll
                for (int i = 0; i < 4; i++)
                    acc[j][i] += q[j] * k[i];
        }
        // scale + causal mask, store transposed
        #pragma unroll
        for (int i = 0; i < 4; i++) {
            int kg = k0 + cS + i;
            #pragma unroll
            for (int j = 0; j < 4; j++) {
                int qg = q0 + rbase + j;
                Pt[(cS + i) * QT_LD + rbase + j] =
                    (kg <= qg) ? acc[j][i] * scale : -1e30f;
            }
        }
        __syncthreads();

        // Online softmax: thread r (< 64) owns row r (conflict-free column walk)
        if (tid < 64) {
            const int r = tid;
            float mo = mS[r], mn = mo;
            #pragma unroll 8
            for (int c = 0; c < 64; c++) mn = fmaxf(mn, Pt[c * QT_LD + r]);
            float al = __expf(mo - mn);
            float ls = 0.f;
            #pragma unroll 8
            for (int c = 0; c < 64; c++) {
                float p = __expf(Pt[c * QT_LD + r] - mn);
                Pt[c * QT_LD + r] = p;
                ls += p;
            }
            lS[r] = lS[r] * al + ls;
            mS[r] = mn;
            aS[r] = al;
        }
        __syncthreads();

        // O = O * alpha + P @ V, each thread 4 rows x 8 cols
        float al4[4];
        #pragma unroll
        for (int j = 0; j < 4; j++) al4[j] = aS[rbase + j];
        #pragma unroll
        for (int j = 0; j < 4; j++)
            #pragma unroll
            for (int i = 0; i < 8; i++) O[j][i] *= al4[j];

        #pragma unroll 4
        for (int c = 0; c < 64; c++) {
            float4 pv = *(float4*)(Pt + c * QT_LD + rbase);
            float p[4] = {pv.x, pv.y, pv.z, pv.w};
            float4 v0 = *(float4*)(Vs + c * 128 + cV);
            float4 v1 = *(float4*)(Vs + c * 128 + cV + 4);
            float v[8] = {v0.x, v0.y, v0.z, v0.w, v1.x, v1.y, v1.z, v1.w};
            #pragma unroll
            for (int j = 0; j < 4; j++)
                #pragma unroll
                for (int i = 0; i < 8; i++)
                    O[j][i] += p[j] * v[i];
        }
    }

    // Epilogue: divide by l, write [b, q, h*128 + c] as rows of [MTOK, 4096]
    float linv[4];
    #pragma unroll
    for (int j = 0; j < 4; j++) linv[j] = 1.f / lS[rbase + j];
    #pragma unroll
    for (int j = 0; j < 4; j++) {
        float* orow = attn + (size_t)(b * SEQ + q0 + rbase + j) * DMODEL + h * HD + cV;
        *(float4*)orow = make_float4(O[j][0] * linv[j], O[j][1] * linv[j],
                                     O[j][2] * linv[j], O[j][3] * linv[j]);
        *((float4*)orow + 1) = make_float4(O[j][4] * linv[j], O[j][5] * linv[j],
                                           O[j][6] * linv[j], O[j][7] * linv[j]);
    }
}

// ---------------------------------------------------------------------------
extern "C" void kernel_launch(void* const* d_in, const int* in_sizes, int n_in,
                              void* d_out, int out_size)
{
    const float* hidden = (const float*)d_in[0];
    const float* cosT   = (const float*)d_in[1];
    const float* sinT   = (const float*)d_in[2];
    const float* Wqkv   = (const float*)d_in[3];
    const float* Wout   = (const float*)d_in[4];
    float* out = (float*)d_out;

    float *qkv, *attn;
    cudaGetSymbolAddress((void**)&qkv, g_qkv);
    cudaGetSymbolAddress((void**)&attn, g_attn);

    // 1) QKV projection: [4096,4096] @ [4096,6144]
    sgemm128<<<dim3(QKVD / 128, MTOK / 128), 256>>>(hidden, Wqkv, qkv,
                                                    MTOK, QKVD, DMODEL);
    // 2) RoPE on Q and K heads in-place
    rope_kernel<<<dim3(MTOK, NHEADS + NKV), 64>>>(qkv, cosT, sinT);

    // 3) Causal GQA flash attention
    cudaFuncSetAttribute(flash_kernel,
                         cudaFuncAttributeMaxDynamicSharedMemorySize,
                         FLASH_SMEM_BYTES);
    flash_kernel<<<dim3(SEQ / 64, BATCH * NHEADS), 256, FLASH_SMEM_BYTES>>>(qkv, attn);

    // 4) Output projection: [4096,4096] @ [4096,4096]
    sgemm128<<<dim3(DMODEL / 128, MTOK / 128), 256>>>(attn, Wout, out,
                                                      MTOK, DMODEL, DMODEL);
}

// round 3
// speedup vs baseline: 2.0000x; 2.0000x over previous
#include <cuda_runtime.h>
#include <math.h>
#include <stdint.h>

#define BATCH   2
#define SEQ     2048
#define DMODEL  4096
#define NHEADS  32
#define NKV     8
#define HD      128
#define QKVD    6144            // (32 + 2*8) * 128
#define MTOK    (BATCH * SEQ)   // 4096

// Scratch (allocation-free rule: __device__ globals)
__device__ float g_X   [(size_t)MTOK * DMODEL];   // tf32-rounded hidden
__device__ float g_qkv [(size_t)MTOK * QKVD];
__device__ float g_attn[(size_t)MTOK * DMODEL];   // tf32-rounded attn out
__device__ float g_WqT [(size_t)QKVD * DMODEL];   // Wqkv^T, tf32-rounded
__device__ float g_WoT [(size_t)DMODEL * DMODEL]; // Wout^T, tf32-rounded

// ---------------------------------------------------------------------------
// Helpers (baseline PTX only — no sm_103a-exclusive features)
// ---------------------------------------------------------------------------
__device__ __forceinline__ uint32_t s2u(const void* p) {
    uint32_t a;
    asm("{ .reg .u64 t; cvta.to.shared.u64 t, %1; cvt.u32.u64 %0, t; }"
        : "=r"(a) : "l"(p));
    return a;
}
__device__ __forceinline__ float tf32r(float x) {
    float y; asm("cvt.rna.tf32.f32 %0, %1;" : "=f"(y) : "f"(x)); return y;
}
__device__ __forceinline__ void cp_async16(uint32_t dst, const void* src) {
    asm volatile("cp.async.cg.shared.global [%0], [%1], 16;"
                 :: "r"(dst), "l"(src) : "memory");
}
__device__ __forceinline__ void mma_tf32(float* c, const uint32_t* a,
                                         const uint32_t* b) {
    asm volatile(
        "mma.sync.aligned.m16n8k8.row.col.f32.tf32.tf32.f32 "
        "{%0,%1,%2,%3}, {%4,%5,%6,%7}, {%8,%9}, {%0,%1,%2,%3};"
        : "+f"(c[0]), "+f"(c[1]), "+f"(c[2]), "+f"(c[3])
        : "r"(a[0]), "r"(a[1]), "r"(a[2]), "r"(a[3]), "r"(b[0]), "r"(b[1]));
}

// ---------------------------------------------------------------------------
// Prep kernels: tf32 rounding + transpose
// ---------------------------------------------------------------------------
__global__ void round_tf32_kernel(const float4* __restrict__ in,
                                  float4* __restrict__ out, int n4) {
    for (int i = blockIdx.x * blockDim.x + threadIdx.x; i < n4;
         i += gridDim.x * blockDim.x) {
        float4 v = in[i];
        v.x = tf32r(v.x); v.y = tf32r(v.y); v.z = tf32r(v.z); v.w = tf32r(v.w);
        out[i] = v;
    }
}

// in: [R][C] row-major -> out: [C][R] row-major, rounded to tf32.
__global__ void transpose_tf32_kernel(const float* __restrict__ in,
                                      float* __restrict__ out, int R, int C) {
    __shared__ float t[32][33];
    int cb = blockIdx.x * 32, rb = blockIdx.y * 32;
    int tx = threadIdx.x, ty = threadIdx.y;
    #pragma unroll
    for (int i = 0; i < 4; i++)
        t[ty + i * 8][tx] = tf32r(in[(size_t)(rb + ty + i * 8) * C + cb + tx]);
    __syncthreads();
    #pragma unroll
    for (int i = 0; i < 4; i++)
        out[(size_t)(cb + ty + i * 8) * R + rb + tx] = t[tx][ty + i * 8];
}

// ---------------------------------------------------------------------------
// mma.sync tf32 GEMM: C[M,N] = A[M,K] @ Bt[N,K]^T   (A, Bt row-major K-major)
// CTA tile 128x128, BK=32, 256 threads = 8 warps (2M x 4N), warp tile 64x32.
// Double-buffered cp.async. smem padded [128][36] -> conflict-free frag LDS.
// ---------------------------------------------------------------------------
#define BKP 36
#define GEMM_STAGE_FLOATS (2 * 128 * BKP)              // A + B per stage
#define GEMM_SMEM_BYTES   (2 * GEMM_STAGE_FLOATS * 4)  // 73728

__global__ __launch_bounds__(256) void gemm_mma_tf32(
    const float* __restrict__ A, const float* __restrict__ Bt,
    float* __restrict__ C, int N, int K)
{
    extern __shared__ float sm[];
    // stage s: A at sm + s*STAGE, B at sm + s*STAGE + 128*BKP

    const int tid  = threadIdx.x;
    const int wid  = tid >> 5;
    const int lane = tid & 31;
    const int gid  = lane >> 2;    // 0..7
    const int tig  = lane & 3;     // 0..3
    const int wm   = (wid >> 2) * 64;   // warp M offset in CTA tile
    const int wn   = (wid & 3) * 32;    // warp N offset
    const int m0 = blockIdx.y * 128;
    const int n0 = blockIdx.x * 128;
    const uint32_t sb = s2u(sm);

    const float* Ab = A  + (size_t)m0 * K;
    const float* Bb = Bt + (size_t)n0 * K;
    const int NC = K >> 5;

    // Per-thread load slots: 4 float4 for A, 4 for B (tile 128x32 = 1024 f4)
    const int lr = tid >> 3;           // rows 0..31 handled 4x (stride 32)
    const int lc = (tid & 7) * 4;      // float4 col within 32-float row

    #define LOAD_CHUNK(kc, s)                                                  \
    {                                                                          \
        uint32_t abase = sb + (s) * GEMM_STAGE_FLOATS * 4;                     \
        uint32_t bbase = abase + 128 * BKP * 4;                                \
        _Pragma("unroll")                                                      \
        for (int i = 0; i < 4; i++) {                                          \
            int r = lr + i * 32;                                               \
            uint32_t off = (uint32_t)(r * BKP + lc) * 4;                       \
            cp_async16(abase + off, Ab + (size_t)r * K + (kc) * 32 + lc);      \
            cp_async16(bbase + off, Bb + (size_t)r * K + (kc) * 32 + lc);      \
        }                                                                      \
        asm volatile("cp.async.commit_group;" ::: "memory");                   \
    }

    float acc[4][4][4];
    #pragma unroll
    for (int mi = 0; mi < 4; mi++)
        #pragma unroll
        for (int ni = 0; ni < 4; ni++)
            #pragma unroll
            for (int q = 0; q < 4; q++) acc[mi][ni][q] = 0.f;

    LOAD_CHUNK(0, 0);

    for (int kc = 0; kc < NC; kc++) {
        const int s = kc & 1;
        asm volatile("cp.async.wait_group 0;" ::: "memory");
        __syncthreads();
        if (kc + 1 < NC) LOAD_CHUNK(kc + 1, s ^ 1);

        const float* As = sm + s * GEMM_STAGE_FLOATS;
        const float* Bs = As + 128 * BKP;

        #pragma unroll
        for (int ks = 0; ks < 4; ks++) {
            const int k0 = ks * 8;
            uint32_t af[4][4], bf[4][2];
            #pragma unroll
            for (int mi = 0; mi < 4; mi++) {
                const float* ap = As + (wm + mi * 16 + gid) * BKP + k0 + tig;
                af[mi][0] = __float_as_uint(ap[0]);
                af[mi][1] = __float_as_uint(ap[8 * BKP]);
                af[mi][2] = __float_as_uint(ap[4]);
                af[mi][3] = __float_as_uint(ap[8 * BKP + 4]);
            }
            #pragma unroll
            for (int ni = 0; ni < 4; ni++) {
                const float* bp = Bs + (wn + ni * 8 + gid) * BKP + k0 + tig;
                bf[ni][0] = __float_as_uint(bp[0]);
                bf[ni][1] = __float_as_uint(bp[4]);
            }
            #pragma unroll
            for (int mi = 0; mi < 4; mi++)
                #pragma unroll
                for (int ni = 0; ni < 4; ni++)
                    mma_tf32(acc[mi][ni], af[mi], bf[ni]);
        }
        __syncthreads();
    }

    // Epilogue: c0,c1 adjacent cols -> float2 stores
    #pragma unroll
    for (int mi = 0; mi < 4; mi++) {
        const int r0 = m0 + wm + mi * 16 + gid;
        #pragma unroll
        for (int ni = 0; ni < 4; ni++) {
            const int c = n0 + wn + ni * 8 + 2 * tig;
            *(float2*)(C + (size_t)r0 * N + c) =
                make_float2(acc[mi][ni][0], acc[mi][ni][1]);
            *(float2*)(C + (size_t)(r0 + 8) * N + c) =
                make_float2(acc[mi][ni][2], acc[mi][ni][3]);
        }
    }
}

// ---------------------------------------------------------------------------
// RoPE in-place on Q (heads 0..31) and K (heads 32..39) parts of qkv.
// ---------------------------------------------------------------------------
__global__ void rope_kernel(float* __restrict__ qkv,
                            const float* __restrict__ cosT,
                            const float* __restrict__ sinT)
{
    const int token = blockIdx.x;
    const int head  = blockIdx.y;
    const int s = token & (SEQ - 1);
    const int d = threadIdx.x;      // 0..63

    float* p = qkv + (size_t)token * QKVD + head * HD;
    const float c  = cosT[s * HD + d];
    const float sn = sinT[s * HD + d];
    const float x1 = p[d];
    const float x2 = p[d + 64];
    p[d]      = x1 * c - x2 * sn;
    p[d + 64] = x2 * c + x1 * sn;
}

// ---------------------------------------------------------------------------
// FP32 flash attention, causal GQA. BQ = BK = 64, 256 threads.
// ---------------------------------------------------------------------------
#define QT_LD 68
#define FLASH_SMEM_FLOATS (128*QT_LD*2 + 64*128 + 64*QT_LD + 3*64)
#define FLASH_SMEM_BYTES  (FLASH_SMEM_FLOATS * 4)

__global__ __launch_bounds__(256) void flash_kernel(
    const float* __restrict__ qkv, float* __restrict__ attn)
{
    extern __shared__ float sm[];
    float* Qt = sm;
    float* Kt = Qt + 128 * QT_LD;
    float* Vs = Kt + 128 * QT_LD;
    float* Pt = Vs + 64 * 128;
    float* mS = Pt + 64 * QT_LD;
    float* lS = mS + 64;
    float* aS = lS + 64;

    const int tid = threadIdx.x;
    const int qt  = blockIdx.x;
    const int bh  = blockIdx.y;
    const int b   = bh >> 5;
    const int h   = bh & 31;
    const int kvh = h >> 2;
    const int q0  = qt * 64;
    const float scale = 0.08838834764831845f;

    const float* Qg = qkv + (size_t)b * SEQ * QKVD + (size_t)h * HD;
    const float* Kg = qkv + (size_t)b * SEQ * QKVD + NHEADS * HD + (size_t)kvh * HD;
    const float* Vg = Kg + NKV * HD;

    #pragma unroll
    for (int i = 0; i < 8; i++) {
        int idx = i * 256 + tid;
        int r = idx >> 5, d4 = (idx & 31) << 2;
        float4 v = *(const float4*)(Qg + (size_t)(q0 + r) * QKVD + d4);
        Qt[(d4 + 0) * QT_LD + r] = v.x;
        Qt[(d4 + 1) * QT_LD + r] = v.y;
        Qt[(d4 + 2) * QT_LD + r] = v.z;
        Qt[(d4 + 3) * QT_LD + r] = v.w;
    }
    if (tid < 64) { mS[tid] = -INFINITY; lS[tid] = 0.f; }

    const int rt = tid >> 4, ct = tid & 15;
    const int rbase = rt << 2;
    const int cS = ct << 2;
    const int cV = ct << 3;

    float O[4][8];
    #pragma unroll
    for (int j = 0; j < 4; j++)
        #pragma unroll
        for (int i = 0; i < 8; i++) O[j][i] = 0.f;

    for (int kt = 0; kt <= qt; kt++) {
        const int k0 = kt * 64;
        __syncthreads();

        #pragma unroll
        for (int i = 0; i < 8; i++) {
            int idx = i * 256 + tid;
            int r = idx >> 5, d4 = (idx & 31) << 2;
            float4 kv = *(const float4*)(Kg + (size_t)(k0 + r) * QKVD + d4);
            Kt[(d4 + 0) * QT_LD + r] = kv.x;
            Kt[(d4 + 1) * QT_LD + r] = kv.y;
            Kt[(d4 + 2) * QT_LD + r] = kv.z;
            Kt[(d4 + 3) * QT_LD + r] = kv.w;
            float4 vv = *(const float4*)(Vg + (size_t)(k0 + r) * QKVD + d4);
            *(float4*)(Vs + r * 128 + d4) = vv;
        }
        __syncthreads();

        float acc[4][4] = {};
        #pragma unroll 8
        for (int d = 0; d < 128; d++) {
            float4 qv = *(float4*)(Qt + d * QT_LD + rbase);
            float4 kv = *(float4*)(Kt + d * QT_LD + cS);
            float q[4] = {qv.x, qv.y, qv.z, qv.w};
            float k[4] = {kv.x, kv.y, kv.z, kv.w};
            #pragma unroll
            for (int j = 0; j < 4; j++)
                #pragma unroll
                for (int i = 0; i < 4; i++)
                    acc[j][i] += q[j] * k[i];
        }
        #pragma unroll
        for (int i = 0; i < 4; i++) {
            int kg = k0 + cS + i;
            #pragma unroll
            for (int j = 0; j < 4; j++) {
                int qg = q0 + rbase + j;
                Pt[(cS + i) * QT_LD + rbase + j] =
                    (kg <= qg) ? acc[j][i] * scale : -1e30f;
            }
        }
        __syncthreads();

        if (tid < 64) {
            const int r = tid;
            float mo = mS[r], mn = mo;
            #pragma unroll 8
            for (int c = 0; c < 64; c++) mn = fmaxf(mn, Pt[c * QT_LD + r]);
            float al = __expf(mo - mn);
            float ls = 0.f;
            #pragma unroll 8
            for (int c = 0; c < 64; c++) {
                float p = __expf(Pt[c * QT_LD + r] - mn);
                Pt[c * QT_LD + r] = p;
                ls += p;
            }
            lS[r] = lS[r] * al + ls;
            mS[r] = mn;
            aS[r] = al;
        }
        __syncthreads();

        float al4[4];
        #pragma unroll
        for (int j = 0; j < 4; j++) al4[j] = aS[rbase + j];
        #pragma unroll
        for (int j = 0; j < 4; j++)
            #pragma unroll
            for (int i = 0; i < 8; i++) O[j][i] *= al4[j];

        #pragma unroll 4
        for (int c = 0; c < 64; c++) {
            float4 pv = *(float4*)(Pt + c * QT_LD + rbase);
            float p[4] = {pv.x, pv.y, pv.z, pv.w};
            float4 v0 = *(float4*)(Vs + c * 128 + cV);
            float4 v1 = *(float4*)(Vs + c * 128 + cV + 4);
            float v[8] = {v0.x, v0.y, v0.z, v0.w, v1.x, v1.y, v1.z, v1.w};
            #pragma unroll
            for (int j = 0; j < 4; j++)
                #pragma unroll
                for (int i = 0; i < 8; i++)
                    O[j][i] += p[j] * v[i];
        }
    }

    float linv[4];
    #pragma unroll
    for (int j = 0; j < 4; j++) linv[j] = 1.f / lS[rbase + j];
    #pragma unroll
    for (int j = 0; j < 4; j++) {
        float* orow = attn + (size_t)(b * SEQ + q0 + rbase + j) * DMODEL + h * HD + cV;
        *(float4*)orow = make_float4(tf32r(O[j][0] * linv[j]), tf32r(O[j][1] * linv[j]),
                                     tf32r(O[j][2] * linv[j]), tf32r(O[j][3] * linv[j]));
        *((float4*)orow + 1) = make_float4(tf32r(O[j][4] * linv[j]), tf32r(O[j][5] * linv[j]),
                                           tf32r(O[j][6] * linv[j]), tf32r(O[j][7] * linv[j]));
    }
}

// ---------------------------------------------------------------------------
extern "C" void kernel_launch(void* const* d_in, const int* in_sizes, int n_in,
                              void* d_out, int out_size)
{
    const float* hidden = (const float*)d_in[0];
    const float* cosT   = (const float*)d_in[1];
    const float* sinT   = (const float*)d_in[2];
    const float* Wqkv   = (const float*)d_in[3];
    const float* Wout   = (const float*)d_in[4];
    float* out = (float*)d_out;

    float *X, *qkv, *attn, *WqT, *WoT;
    cudaGetSymbolAddress((void**)&X,    g_X);
    cudaGetSymbolAddress((void**)&qkv,  g_qkv);
    cudaGetSymbolAddress((void**)&attn, g_attn);
    cudaGetSymbolAddress((void**)&WqT,  g_WqT);
    cudaGetSymbolAddress((void**)&WoT,  g_WoT);

    cudaFuncSetAttribute(gemm_mma_tf32,
                         cudaFuncAttributeMaxDynamicSharedMemorySize,
                         GEMM_SMEM_BYTES);
    cudaFuncSetAttribute(flash_kernel,
                         cudaFuncAttributeMaxDynamicSharedMemorySize,
                         FLASH_SMEM_BYTES);

    // 0) tf32-round X; transpose+round weights
    round_tf32_kernel<<<2048, 256>>>((const float4*)hidden, (float4*)X,
                                     MTOK * DMODEL / 4);
    transpose_tf32_kernel<<<dim3(QKVD / 32, DMODEL / 32), dim3(32, 8)>>>(
        Wqkv, WqT, DMODEL, QKVD);
    transpose_tf32_kernel<<<dim3(DMODEL / 32, DMODEL / 32), dim3(32, 8)>>>(
        Wout, WoT, DMODEL, DMODEL);

    // 1) QKV projection (tensor cores, mma.sync tf32)
    gemm_mma_tf32<<<dim3(QKVD / 128, MTOK / 128), 256, GEMM_SMEM_BYTES>>>(
        X, WqT, qkv, QKVD, DMODEL);

    // 2) RoPE
    rope_kernel<<<dim3(MTOK, NHEADS + NKV), 64>>>(qkv, cosT, sinT);

    // 3) Causal GQA flash attention (fp32)
    flash_kernel<<<dim3(SEQ / 64, BATCH * NHEADS), 256, FLASH_SMEM_BYTES>>>(qkv, attn);

    // 4) Output projection (tensor cores)
    gemm_mma_tf32<<<dim3(DMODEL / 128, MTOK / 128), 256, GEMM_SMEM_BYTES>>>(
        attn, WoT, out, DMODEL, DMODEL);
}

// round 4
// speedup vs baseline: 6.8866x; 3.4433x over previous
#include <cuda_runtime.h>
#include <cuda_fp16.h>
#include <math.h>
#include <stdint.h>

#define BATCH   2
#define SEQ     2048
#define DMODEL  4096
#define NHEADS  32
#define NKV     8
#define HD      128
#define QKVD    6144            // (32 + 2*8) * 128
#define MTOK    (BATCH * SEQ)   // 4096

// Scratch (allocation-free rule: __device__ globals)
__device__ float  g_qkv  [(size_t)MTOK * QKVD];     // fp32 qkv (GEMM1 out)
__device__ __half g_Xh   [(size_t)MTOK * DMODEL];   // hidden fp16
__device__ __half g_WqTh [(size_t)QKVD * DMODEL];   // Wqkv^T fp16
__device__ __half g_WoTh [(size_t)DMODEL * DMODEL]; // Wout^T fp16
__device__ __half g_Qh   [(size_t)BATCH * NHEADS * SEQ * HD]; // rope'd Q fp16
__device__ __half g_Kh   [(size_t)BATCH * NKV * SEQ * HD];    // rope'd K fp16
__device__ __half g_Vt   [(size_t)BATCH * NKV * HD * SEQ];    // V transposed fp16
__device__ __half g_attnH[(size_t)MTOK * DMODEL];   // attention out fp16

// ---------------------------------------------------------------------------
// Helpers (baseline PTX only)
// ---------------------------------------------------------------------------
__device__ __forceinline__ uint32_t s2u(const void* p) {
    uint32_t a;
    asm("{ .reg .u64 t; cvta.to.shared.u64 t, %1; cvt.u32.u64 %0, t; }"
        : "=r"(a) : "l"(p));
    return a;
}
__device__ __forceinline__ void cp_async16(uint32_t dst, const void* src) {
    asm volatile("cp.async.cg.shared.global [%0], [%1], 16;"
                 :: "r"(dst), "l"(src) : "memory");
}
__device__ __forceinline__ void mma_f16(float* c, const uint32_t* a,
                                        const uint32_t* b) {
    asm volatile(
        "mma.sync.aligned.m16n8k16.row.col.f32.f16.f16.f32 "
        "{%0,%1,%2,%3}, {%4,%5,%6,%7}, {%8,%9}, {%0,%1,%2,%3};"
        : "+f"(c[0]), "+f"(c[1]), "+f"(c[2]), "+f"(c[3])
        : "r"(a[0]), "r"(a[1]), "r"(a[2]), "r"(a[3]), "r"(b[0]), "r"(b[1]));
}
__device__ __forceinline__ uint32_t packh2(float x, float y) {
    __half2 h = __floats2half2_rn(x, y);
    return *(uint32_t*)&h;
}

// ---------------------------------------------------------------------------
// Prep kernels
// ---------------------------------------------------------------------------
__global__ void f32_to_f16_kernel(const float4* __restrict__ in,
                                  __half2* __restrict__ out, int n4) {
    for (int i = blockIdx.x * blockDim.x + threadIdx.x; i < n4;
         i += gridDim.x * blockDim.x) {
        float4 v = in[i];
        out[2 * i]     = __floats2half2_rn(v.x, v.y);
        out[2 * i + 1] = __floats2half2_rn(v.z, v.w);
    }
}

// in fp32 [R][C] row-major -> out fp16 [C][R] row-major.
__global__ void transpose_f16_kernel(const float* __restrict__ in,
                                     __half* __restrict__ out, int R, int C) {
    __shared__ float t[32][33];
    int cb = blockIdx.x * 32, rb = blockIdx.y * 32;
    int tx = threadIdx.x, ty = threadIdx.y;
    #pragma unroll
    for (int i = 0; i < 4; i++)
        t[ty + i * 8][tx] = in[(size_t)(rb + ty + i * 8) * C + cb + tx];
    __syncthreads();
    #pragma unroll
    for (int i = 0; i < 4; i++)
        out[(size_t)(cb + ty + i * 8) * R + rb + tx] =
            __float2half_rn(t[tx][ty + i * 8]);
}

// ---------------------------------------------------------------------------
// fp16 mma.sync GEMM: C[M,N](fp32) = A[M,K] @ Bt[N,K]^T  (fp16, K-major)
// CTA tile 128x128, BK=32, 256 thr = 8 warps (2M x 4N), warp 64x32.
// smem LD=40 halves (conflict-free fragment LDS), double-buffered cp.async.
// ---------------------------------------------------------------------------
__global__ __launch_bounds__(256) void gemm_mma_f16(
    const __half* __restrict__ A, const __half* __restrict__ Bt,
    float* __restrict__ C, int N, int K)
{
    __shared__ __half smA[2][128 * 40];
    __shared__ __half smB[2][128 * 40];

    const int tid  = threadIdx.x;
    const int wid  = tid >> 5;
    const int lane = tid & 31;
    const int gid  = lane >> 2;
    const int tig  = lane & 3;
    const int wm   = (wid >> 2) * 64;
    const int wn   = (wid & 3) * 32;
    const int m0 = blockIdx.y * 128;
    const int n0 = blockIdx.x * 128;
    const uint32_t abase = s2u(smA);
    const uint32_t bbase = s2u(smB);

    const __half* Ab = A  + (size_t)m0 * K;
    const __half* Bb = Bt + (size_t)n0 * K;
    const int NC = K >> 5;

    #define LOAD_CHUNK16(kc, s)                                                \
    {                                                                          \
        _Pragma("unroll")                                                      \
        for (int i = 0; i < 4; i++) {                                          \
            int idx = i * 256 + tid;                                           \
            int isB = idx >> 9, r = (idx >> 2) & 127, c8 = idx & 3;            \
            uint32_t dst = (isB ? bbase : abase) + (s) * 10240u +              \
                           (uint32_t)(r * 40 + c8 * 8) * 2;                    \
            const __half* src = (isB ? Bb : Ab) +                              \
                                (size_t)r * K + (kc) * 32 + c8 * 8;            \
            cp_async16(dst, src);                                              \
        }                                                                      \
        asm volatile("cp.async.commit_group;" ::: "memory");                   \
    }

    float acc[4][4][4];
    #pragma unroll
    for (int mi = 0; mi < 4; mi++)
        #pragma unroll
        for (int ni = 0; ni < 4; ni++)
            #pragma unroll
            for (int q = 0; q < 4; q++) acc[mi][ni][q] = 0.f;

    LOAD_CHUNK16(0, 0);

    for (int kc = 0; kc < NC; kc++) {
        const int s = kc & 1;
        asm volatile("cp.async.wait_group 0;" ::: "memory");
        __syncthreads();
        if (kc + 1 < NC) LOAD_CHUNK16(kc + 1, s ^ 1);

        const __half* As = smA[s];
        const __half* Bs = smB[s];

        #pragma unroll
        for (int ks = 0; ks < 2; ks++) {
            const int k0h = ks * 16;
            uint32_t af[4][4], bf[4][2];
            #pragma unroll
            for (int mi = 0; mi < 4; mi++) {
                const __half* ap = As + (wm + mi * 16 + gid) * 40 + k0h + 2 * tig;
                af[mi][0] = *(const uint32_t*)(ap);
                af[mi][1] = *(const uint32_t*)(ap + 8 * 40);
                af[mi][2] = *(const uint32_t*)(ap + 8);
                af[mi][3] = *(const uint32_t*)(ap + 8 * 40 + 8);
            }
            #pragma unroll
            for (int ni = 0; ni < 4; ni++) {
                const __half* bp = Bs + (wn + ni * 8 + gid) * 40 + k0h + 2 * tig;
                bf[ni][0] = *(const uint32_t*)(bp);
                bf[ni][1] = *(const uint32_t*)(bp + 8);
            }
            #pragma unroll
            for (int mi = 0; mi < 4; mi++)
                #pragma unroll
                for (int ni = 0; ni < 4; ni++)
                    mma_f16(acc[mi][ni], af[mi], bf[ni]);
        }
        __syncthreads();
    }

    #pragma unroll
    for (int mi = 0; mi < 4; mi++) {
        const int r0 = m0 + wm + mi * 16 + gid;
        #pragma unroll
        for (int ni = 0; ni < 4; ni++) {
            const int c = n0 + wn + ni * 8 + 2 * tig;
            *(float2*)(C + (size_t)r0 * N + c) =
                make_float2(acc[mi][ni][0], acc[mi][ni][1]);
            *(float2*)(C + (size_t)(r0 + 8) * N + c) =
                make_float2(acc[mi][ni][2], acc[mi][ni][3]);
        }
    }
}

// ---------------------------------------------------------------------------
// RoPE + pack: fp32 qkv -> fp16 Qh [b][h][s][d], Kh [b][kv][s][d]
// ---------------------------------------------------------------------------
__global__ void rope_pack_kernel(const float* __restrict__ qkv,
                                 const float* __restrict__ cosT,
                                 const float* __restrict__ sinT,
                                 __half* __restrict__ Qh,
                                 __half* __restrict__ Kh)
{
    const int token = blockIdx.x;
    const int head  = blockIdx.y;   // 0..39
    const int b = token >> 11;
    const int s = token & (SEQ - 1);
    const int d = threadIdx.x;      // 0..63

    const float* p = qkv + (size_t)token * QKVD + head * HD;
    const float c  = cosT[s * HD + d];
    const float sn = sinT[s * HD + d];
    const float x1 = p[d];
    const float x2 = p[d + 64];
    const float o1 = x1 * c - x2 * sn;
    const float o2 = x2 * c + x1 * sn;

    __half* dst = (head < NHEADS)
        ? Qh + ((size_t)(b * NHEADS + head) * SEQ + s) * HD
        : Kh + ((size_t)(b * NKV + head - NHEADS) * SEQ + s) * HD;
    dst[d]      = __float2half_rn(o1);
    dst[d + 64] = __float2half_rn(o2);
}

// V pack: fp32 qkv V region -> fp16 transposed Vt [b][kv][d][s]
__global__ void v_pack_kernel(const float* __restrict__ qkv,
                              __half* __restrict__ Vt)
{
    __shared__ float t[32][33];
    const int sx = blockIdx.x * 32;       // seq
    const int dy = blockIdx.y * 32;       // dim
    const int bkv = blockIdx.z;           // 0..15
    const int b = bkv >> 3, kvh = bkv & 7;
    const int tx = threadIdx.x, ty = threadIdx.y;

    #pragma unroll
    for (int i = 0; i < 4; i++)
        t[ty + i * 8][tx] = qkv[(size_t)(b * SEQ + sx + ty + i * 8) * QKVD +
                                (NHEADS + NKV) * HD + kvh * HD + dy + tx];
    __syncthreads();
    #pragma unroll
    for (int i = 0; i < 4; i++)
        Vt[((size_t)(b * NKV + kvh) * HD + dy + ty + i * 8) * SEQ + sx + tx] =
            __float2half_rn(t[tx][ty + i * 8]);
}

// ---------------------------------------------------------------------------
// Flash attention on mma.sync fp16. BQ=128, BK=64, 256 thr = 8 warps,
// warp owns 16 q rows. Q frags in registers, P in registers (FA2 style),
// fp32 online softmax, double-buffered cp.async K/Vt tiles.
// ---------------------------------------------------------------------------
#define QLD 136
#define KLD 136
#define VLD 72
#define K_TILE_B (64 * KLD * 2)     // 17408
#define V_TILE_B (128 * VLD * 2)    // 18432
#define STAGE_B  (K_TILE_B + V_TILE_B)   // 35840
#define FLASH_SMEM (2 * STAGE_B)         // 71680

__global__ __launch_bounds__(256) void flash_mma(
    const __half* __restrict__ Qh, const __half* __restrict__ Kh,
    const __half* __restrict__ Vt, __half* __restrict__ attnH)
{
    extern __shared__ char dsm[];
    const int tid = threadIdx.x;
    const int wid = tid >> 5, lane = tid & 31;
    const int gid = lane >> 2, tig = lane & 3;
    const int qt = (gridDim.x - 1) - blockIdx.x;   // heavy tiles first
    const int bh = blockIdx.y;
    const int b = bh >> 5, h = bh & 31, kvh = h >> 2;
    const int q0 = qt * 128;
    const uint32_t sb = s2u(dsm);
    const float scale = 0.08838834764831845f;

    const __half* Qg = Qh + ((size_t)(b * NHEADS + h) * SEQ + q0) * HD;
    const __half* Kg = Kh + (size_t)(b * NKV + kvh) * SEQ * HD;
    const __half* Vg = Vt + (size_t)(b * NKV + kvh) * HD * SEQ;

    // Stage Q tile (128 x 128 halves) into smem, extract frags to registers.
    #pragma unroll
    for (int i = 0; i < 8; i++) {
        int idx = i * 256 + tid;
        int r = idx >> 4, c = idx & 15;
        cp_async16(sb + (uint32_t)(r * QLD + c * 8) * 2,
                   Qg + (size_t)r * HD + c * 8);
    }
    asm volatile("cp.async.commit_group;" ::: "memory");
    asm volatile("cp.async.wait_group 0;" ::: "memory");
    __syncthreads();

    uint32_t qf[8][4];
    {
        const __half* Qs = (const __half*)dsm;
        const int row = wid * 16 + gid;
        #pragma unroll
        for (int kk = 0; kk < 8; kk++) {
            const __half* qp = Qs + row * QLD + kk * 16 + 2 * tig;
            qf[kk][0] = *(const uint32_t*)(qp);
            qf[kk][1] = *(const uint32_t*)(qp + 8 * QLD);
            qf[kk][2] = *(const uint32_t*)(qp + 8);
            qf[kk][3] = *(const uint32_t*)(qp + 8 * QLD + 8);
        }
    }
    __syncthreads();

    #define LOADKV(kt, st)                                                     \
    {                                                                          \
        const int k0_ = (kt) * 64;                                             \
        uint32_t base_ = sb + (st) * STAGE_B;                                  \
        _Pragma("unroll")                                                      \
        for (int i_ = 0; i_ < 4; i_++) {                                       \
            int idx_ = i_ * 256 + tid;                                         \
            int r_ = idx_ >> 4, c_ = idx_ & 15;                                \
            cp_async16(base_ + (uint32_t)(r_ * KLD + c_ * 8) * 2,              \
                       Kg + (size_t)(k0_ + r_) * HD + c_ * 8);                 \
        }                                                                      \
        _Pragma("unroll")                                                      \
        for (int i_ = 0; i_ < 4; i_++) {                                       \
            int idx_ = i_ * 256 + tid;                                         \
            int d_ = idx_ >> 3, c_ = idx_ & 7;                                 \
            cp_async16(base_ + K_TILE_B + (uint32_t)(d_ * VLD + c_ * 8) * 2,   \
                       Vg + (size_t)d_ * SEQ + k0_ + c_ * 8);                  \
        }                                                                      \
        asm volatile("cp.async.commit_group;" ::: "memory");                   \
    }

    float Of[16][4];
    #pragma unroll
    for (int ni = 0; ni < 16; ni++)
        #pragma unroll
        for (int q = 0; q < 4; q++) Of[ni][q] = 0.f;
    float m0 = -INFINITY, m1 = -INFINITY, l0 = 0.f, l1 = 0.f;
    const int nkt = 2 * qt + 2;

    LOADKV(0, 0);

    for (int kt = 0; kt < nkt; kt++) {
        const int s = kt & 1;
        asm volatile("cp.async.wait_group 0;" ::: "memory");
        __syncthreads();
        if (kt + 1 < nkt) LOADKV(kt + 1, s ^ 1);

        const __half* Ks = (const __half*)(dsm + s * STAGE_B);
        const __half* Vs = (const __half*)(dsm + s * STAGE_B + K_TILE_B);
        const int k0 = kt * 64;

        // S = Q K^T for this 128x64 tile (per warp: 16x64)
        float S[8][4];
        #pragma unroll
        for (int ni = 0; ni < 8; ni++) {
            S[ni][0] = S[ni][1] = S[ni][2] = S[ni][3] = 0.f;
            const __half* kp = Ks + (ni * 8 + gid) * KLD + 2 * tig;
            #pragma unroll
            for (int kk = 0; kk < 8; kk++) {
                uint32_t bb[2];
                bb[0] = *(const uint32_t*)(kp + kk * 16);
                bb[1] = *(const uint32_t*)(kp + kk * 16 + 8);
                mma_f16(S[ni], qf[kk], bb);
            }
        }

        // mask + scale
        const int row0 = q0 + wid * 16 + gid, row1 = row0 + 8;
        #pragma unroll
        for (int ni = 0; ni < 8; ni++) {
            const int col = k0 + ni * 8 + 2 * tig;
            S[ni][0] = (col     <= row0) ? S[ni][0] * scale : -1e30f;
            S[ni][1] = (col + 1 <= row0) ? S[ni][1] * scale : -1e30f;
            S[ni][2] = (col     <= row1) ? S[ni][2] * scale : -1e30f;
            S[ni][3] = (col + 1 <= row1) ? S[ni][3] * scale : -1e30f;
        }

        // online softmax (rows row0, row1 per thread; reduce across quad)
        float mx0 = fmaxf(S[0][0], S[0][1]), mx1 = fmaxf(S[0][2], S[0][3]);
        #pragma unroll
        for (int ni = 1; ni < 8; ni++) {
            mx0 = fmaxf(mx0, fmaxf(S[ni][0], S[ni][1]));
            mx1 = fmaxf(mx1, fmaxf(S[ni][2], S[ni][3]));
        }
        mx0 = fmaxf(mx0, __shfl_xor_sync(0xFFFFFFFFu, mx0, 1));
        mx0 = fmaxf(mx0, __shfl_xor_sync(0xFFFFFFFFu, mx0, 2));
        mx1 = fmaxf(mx1, __shfl_xor_sync(0xFFFFFFFFu, mx1, 1));
        mx1 = fmaxf(mx1, __shfl_xor_sync(0xFFFFFFFFu, mx1, 2));
        const float mn0 = fmaxf(m0, mx0), mn1 = fmaxf(m1, mx1);
        const float a0 = __expf(m0 - mn0), a1 = __expf(m1 - mn1);
        float s0 = 0.f, s1 = 0.f;
        #pragma unroll
        for (int ni = 0; ni < 8; ni++) {
            S[ni][0] = __expf(S[ni][0] - mn0);
            S[ni][1] = __expf(S[ni][1] - mn0);
            S[ni][2] = __expf(S[ni][2] - mn1);
            S[ni][3] = __expf(S[ni][3] - mn1);
            s0 += S[ni][0] + S[ni][1];
            s1 += S[ni][2] + S[ni][3];
        }
        s0 += __shfl_xor_sync(0xFFFFFFFFu, s0, 1);
        s0 += __shfl_xor_sync(0xFFFFFFFFu, s0, 2);
        s1 += __shfl_xor_sync(0xFFFFFFFFu, s1, 1);
        s1 += __shfl_xor_sync(0xFFFFFFFFu, s1, 2);
        l0 = l0 * a0 + s0;  l1 = l1 * a1 + s1;
        m0 = mn0;  m1 = mn1;

        #pragma unroll
        for (int ni = 0; ni < 16; ni++) {
            Of[ni][0] *= a0; Of[ni][1] *= a0;
            Of[ni][2] *= a1; Of[ni][3] *= a1;
        }

        // P fragments from score registers (A-operand identity)
        uint32_t pf[4][4];
        #pragma unroll
        for (int kk2 = 0; kk2 < 4; kk2++) {
            pf[kk2][0] = packh2(S[2 * kk2][0],     S[2 * kk2][1]);
            pf[kk2][1] = packh2(S[2 * kk2][2],     S[2 * kk2][3]);
            pf[kk2][2] = packh2(S[2 * kk2 + 1][0], S[2 * kk2 + 1][1]);
            pf[kk2][3] = packh2(S[2 * kk2 + 1][2], S[2 * kk2 + 1][3]);
        }

        // O += P @ V
        #pragma unroll
        for (int ni = 0; ni < 16; ni++) {
            const __half* vp = Vs + (ni * 8 + gid) * VLD + 2 * tig;
            #pragma unroll
            for (int kk2 = 0; kk2 < 4; kk2++) {
                uint32_t bb[2];
                bb[0] = *(const uint32_t*)(vp + kk2 * 16);
                bb[1] = *(const uint32_t*)(vp + kk2 * 16 + 8);
                mma_f16(Of[ni], pf[kk2], bb);
            }
        }
    }

    // epilogue: normalize, write fp16 attn
    const float i0 = 1.f / l0, i1 = 1.f / l1;
    const int tok0 = b * SEQ + q0 + wid * 16 + gid;
    #pragma unroll
    for (int ni = 0; ni < 16; ni++) {
        const int col = h * HD + ni * 8 + 2 * tig;
        *(__half2*)(attnH + (size_t)tok0 * DMODEL + col) =
            __floats2half2_rn(Of[ni][0] * i0, Of[ni][1] * i0);
        *(__half2*)(attnH + (size_t)(tok0 + 8) * DMODEL + col) =
            __floats2half2_rn(Of[ni][2] * i1, Of[ni][3] * i1);
    }
}

// ---------------------------------------------------------------------------
extern "C" void kernel_launch(void* const* d_in, const int* in_sizes, int n_in,
                              void* d_out, int out_size)
{
    const float* hidden = (const float*)d_in[0];
    const float* cosT   = (const float*)d_in[1];
    const float* sinT   = (const float*)d_in[2];
    const float* Wqkv   = (const float*)d_in[3];
    const float* Wout   = (const float*)d_in[4];
    float* out = (float*)d_out;

    float  *qkv;
    __half *Xh, *WqTh, *WoTh, *Qh, *Kh, *Vt, *attnH;
    cudaGetSymbolAddress((void**)&qkv,   g_qkv);
    cudaGetSymbolAddress((void**)&Xh,    g_Xh);
    cudaGetSymbolAddress((void**)&WqTh,  g_WqTh);
    cudaGetSymbolAddress((void**)&WoTh,  g_WoTh);
    cudaGetSymbolAddress((void**)&Qh,    g_Qh);
    cudaGetSymbolAddress((void**)&Kh,    g_Kh);
    cudaGetSymbolAddress((void**)&Vt,    g_Vt);
    cudaGetSymbolAddress((void**)&attnH, g_attnH);

    cudaFuncSetAttribute(flash_mma,
                         cudaFuncAttributeMaxDynamicSharedMemorySize,
                         FLASH_SMEM);

    // 0) fp16 conversions
    f32_to_f16_kernel<<<2048, 256>>>((const float4*)hidden, (__half2*)Xh,
                                     MTOK * DMODEL / 4);
    transpose_f16_kernel<<<dim3(QKVD / 32, DMODEL / 32), dim3(32, 8)>>>(
        Wqkv, WqTh, DMODEL, QKVD);
    transpose_f16_kernel<<<dim3(DMODEL / 32, DMODEL / 32), dim3(32, 8)>>>(
        Wout, WoTh, DMODEL, DMODEL);

    // 1) QKV projection (fp16 mma, fp32 out)
    gemm_mma_f16<<<dim3(QKVD / 128, MTOK / 128), 256>>>(Xh, WqTh, qkv,
                                                        QKVD, DMODEL);

    // 2) RoPE + pack to fp16 per-head layouts; V transpose
    rope_pack_kernel<<<dim3(MTOK, NHEADS + NKV), 64>>>(qkv, cosT, sinT, Qh, Kh);
    v_pack_kernel<<<dim3(SEQ / 32, HD / 32, BATCH * NKV), dim3(32, 8)>>>(qkv, Vt);

    // 3) Flash attention on tensor cores
    flash_mma<<<dim3(SEQ / 128, BATCH * NHEADS), 256, FLASH_SMEM>>>(
        Qh, Kh, Vt, attnH);

    // 4) Output projection
    gemm_mma_f16<<<dim3(DMODEL / 128, MTOK / 128), 256>>>(attnH, WoTh, out,
                                                          DMODEL, DMODEL);
}